// round 2
// baseline (speedup 1.0000x reference)
#include <cuda_runtime.h>

// ---------------------------------------------------------------------------
// FrontierLayerVN fused kernel (fp32 baseline)
//
// Pipeline per gathered row m:
//   idx = idx_ligans[m]; sca = S[idx] (256), vec = V[idx] (64x3)
//   vh[h,i]   = sum_c vec[c,i] * Wv1_1[c,h]            (h<64)
//   vn[h]     = ||vh[h,:]||
//   s1[j]     = sum_h vn[h]*Ws1[h,j] + sum_c sca[c]*Ws1[64+c,j]   (j<128)
//   gate[o]   = sigmoid(sum_j s1[j]*Wg1[j,o] + bg1[o])            (o<32)
//   ov[o,i]   = sum_h vh[h,i]*Wv2_1[h,o];  v2 = gate*ov
//   VNLeakyReLU(v2) with Wd1 -> v3
//   s1a       = leaky(s1, 0.01)
//   vh2[h,i]  = sum_c v3[c,i]*Wv1_2[c,h]; vn2 = ||vh2||            (h<32)
//   out[m]    = sum_h vn2[h]*Ws2[h] + sum_j s1a[j]*Ws2[32+j]
// ---------------------------------------------------------------------------

#define NWARPS 8
#define THREADS (NWARPS * 32)

// shared sizes in floats
#define SZ_WV11 4096   // 64x64
#define SZ_WV21 2048   // 64x32
#define SZ_WS1  40960  // 320x128
#define SZ_WG1  4096   // 128x32
#define SZ_BG1  32
#define SZ_WD1  1024   // 32x32
#define SZ_WV12 1024   // 32x32
#define SZ_WS2  160
#define SZ_WEIGHTS (SZ_WV11 + SZ_WV21 + SZ_WS1 + SZ_WG1 + SZ_BG1 + SZ_WD1 + SZ_WV12 + SZ_WS2)
#define SCRATCH_PER_WARP 512
#define SMEM_FLOATS (SZ_WEIGHTS + NWARPS * SCRATCH_PER_WARP)

__global__ __launch_bounds__(THREADS, 1)
void frontier_vn_kernel(
    const float* __restrict__ g_sca,   // (N,256)
    const float* __restrict__ g_vec,   // (N,64,3)
    const int*   __restrict__ g_idx,   // (M,)
    const float* __restrict__ gWv11,   // (64,64)
    const float* __restrict__ gWv21,   // (64,32)
    const float* __restrict__ gWs1,    // (320,128)
    const float* __restrict__ gWg1,    // (128,32)
    const float* __restrict__ gbg1,    // (32,)
    const float* __restrict__ gWd1,    // (32,32)
    const float* __restrict__ gWv12,   // (32,32)
    const float* __restrict__ gWs2,    // (160,)
    float* __restrict__ out,           // (M,)
    int M)
{
    extern __shared__ float sm[];
    float* sWv11 = sm;
    float* sWv21 = sWv11 + SZ_WV11;
    float* sWs1  = sWv21 + SZ_WV21;
    float* sWg1  = sWs1  + SZ_WS1;
    float* sbg1  = sWg1  + SZ_WG1;
    float* sWd1  = sbg1  + SZ_BG1;
    float* sWv12 = sWd1  + SZ_WD1;
    float* sWs2  = sWv12 + SZ_WV12;
    float* scratch = sWs2 + SZ_WS2;

    const int tid = threadIdx.x;

    // ---- cooperative weight staging (float4) ----
    {
        float4* d; const float4* s;
        d = (float4*)sWv11; s = (const float4*)gWv11;
        for (int i = tid; i < SZ_WV11/4; i += THREADS) d[i] = s[i];
        d = (float4*)sWv21; s = (const float4*)gWv21;
        for (int i = tid; i < SZ_WV21/4; i += THREADS) d[i] = s[i];
        d = (float4*)sWs1;  s = (const float4*)gWs1;
        for (int i = tid; i < SZ_WS1/4;  i += THREADS) d[i] = s[i];
        d = (float4*)sWg1;  s = (const float4*)gWg1;
        for (int i = tid; i < SZ_WG1/4;  i += THREADS) d[i] = s[i];
        d = (float4*)sbg1;  s = (const float4*)gbg1;
        for (int i = tid; i < SZ_BG1/4;  i += THREADS) d[i] = s[i];
        d = (float4*)sWd1;  s = (const float4*)gWd1;
        for (int i = tid; i < SZ_WD1/4;  i += THREADS) d[i] = s[i];
        d = (float4*)sWv12; s = (const float4*)gWv12;
        for (int i = tid; i < SZ_WV12/4; i += THREADS) d[i] = s[i];
        d = (float4*)sWs2;  s = (const float4*)gWs2;
        for (int i = tid; i < SZ_WS2/4;  i += THREADS) d[i] = s[i];
    }
    __syncthreads();

    const int warp = tid >> 5;
    const int lane = tid & 31;
    float* ws = scratch + warp * SCRATCH_PER_WARP;
    // scratch regions (floats):
    //  [0,256)   sca        -> later [0,128) s1, [128,224) v2
    //  [256,448) vec        -> later vh   ; [224,320) v3 (vh dead by then)
    //  [448,512) vnorm

    for (int m = blockIdx.x * NWARPS + warp; m < M; m += gridDim.x * NWARPS) {
        const int idx = g_idx[m];
        const float4* gs4 = (const float4*)(g_sca + (size_t)idx * 256);
        const float4* gv4 = (const float4*)(g_vec + (size_t)idx * 192);
        float4 s_a = gs4[lane];
        float4 s_b = gs4[lane + 32];
        float4 v_a = gv4[lane];
        float4 v_b = (lane < 16) ? gv4[lane + 32] : make_float4(0.f,0.f,0.f,0.f);

        __syncwarp();  // prior iteration fully done reading scratch
        ((float4*)ws)[lane]            = s_a;
        ((float4*)ws)[lane + 32]       = s_b;
        ((float4*)(ws + 256))[lane]    = v_a;
        if (lane < 16) ((float4*)(ws + 256))[lane + 32] = v_b;
        __syncwarp();

        // ---- stage 1: vh (lane owns h0=lane, h1=lane+32) ----
        float a0x = 0.f, a0y = 0.f, a0z = 0.f;
        float a1x = 0.f, a1y = 0.f, a1z = 0.f;
        #pragma unroll 8
        for (int c = 0; c < 64; c++) {
            float vx = ws[256 + c*3 + 0];
            float vy = ws[256 + c*3 + 1];
            float vz = ws[256 + c*3 + 2];
            float w0 = sWv11[c*64 + lane];
            float w1 = sWv11[c*64 + 32 + lane];
            a0x += w0*vx; a0y += w0*vy; a0z += w0*vz;
            a1x += w1*vx; a1y += w1*vy; a1z += w1*vz;
        }
        float n0 = sqrtf(a0x*a0x + a0y*a0y + a0z*a0z);
        float n1 = sqrtf(a1x*a1x + a1y*a1y + a1z*a1z);
        __syncwarp();  // everyone done reading vec before overwrite with vh
        ws[256 + lane*3 + 0] = a0x;
        ws[256 + lane*3 + 1] = a0y;
        ws[256 + lane*3 + 2] = a0z;
        ws[256 + (lane+32)*3 + 0] = a1x;
        ws[256 + (lane+32)*3 + 1] = a1y;
        ws[256 + (lane+32)*3 + 2] = a1z;
        ws[448 + lane]      = n0;
        ws[448 + lane + 32] = n1;
        __syncwarp();

        // ---- stage 2: s1[j], lane owns j = lane + 32q ----
        float s0 = 0.f, s1 = 0.f, s2 = 0.f, s3 = 0.f;
        #pragma unroll 8
        for (int k = 0; k < 64; k++) {
            float x = ws[448 + k];
            const float* wr = sWs1 + k * 128;
            s0 += x * wr[lane];
            s1 += x * wr[lane + 32];
            s2 += x * wr[lane + 64];
            s3 += x * wr[lane + 96];
        }
        #pragma unroll 8
        for (int k = 0; k < 256; k++) {
            float x = ws[k];
            const float* wr = sWs1 + (64 + k) * 128;
            s0 += x * wr[lane];
            s1 += x * wr[lane + 32];
            s2 += x * wr[lane + 64];
            s3 += x * wr[lane + 96];
        }
        __syncwarp();  // done reading sca
        ws[lane]      = s0;
        ws[lane + 32] = s1;
        ws[lane + 64] = s2;
        ws[lane + 96] = s3;
        __syncwarp();

        // ---- gate + out_vec (lane owns o = lane) ----
        float g = 0.f;
        #pragma unroll 8
        for (int j = 0; j < 128; j++)
            g += ws[j] * sWg1[j*32 + lane];
        g = 1.f / (1.f + expf(-(g + sbg1[lane])));

        float ox = 0.f, oy = 0.f, oz = 0.f;
        #pragma unroll 8
        for (int h = 0; h < 64; h++) {
            float w = sWv21[h*32 + lane];
            ox += w * ws[256 + h*3 + 0];
            oy += w * ws[256 + h*3 + 1];
            oz += w * ws[256 + h*3 + 2];
        }
        float vx = g * ox, vy = g * oy, vz = g * oz;  // v2[lane]
        __syncwarp();  // done reading vh + s1 region untouched
        ws[128 + lane*3 + 0] = vx;
        ws[128 + lane*3 + 1] = vy;
        ws[128 + lane*3 + 2] = vz;
        __syncwarp();

        // ---- VNLeakyReLU (lane owns o = lane) ----
        float dx = 0.f, dy = 0.f, dz = 0.f;
        #pragma unroll 8
        for (int c = 0; c < 32; c++) {
            float w = sWd1[c*32 + lane];
            dx += w * ws[128 + c*3 + 0];
            dy += w * ws[128 + c*3 + 1];
            dz += w * ws[128 + c*3 + 2];
        }
        float dot = vx*dx + vy*dy + vz*dz;
        float dsq = dx*dx + dy*dy + dz*dz;
        float t = dot / (dsq + 1e-6f);
        float px = vx - t*dx, py = vy - t*dy, pz = vz - t*dz;
        float rx = (dot >= 0.f) ? vx : px;
        float ry = (dot >= 0.f) ? vy : py;
        float rz = (dot >= 0.f) ? vz : pz;
        float ux = 0.2f*vx + 0.8f*rx;
        float uy = 0.2f*vy + 0.8f*ry;
        float uz = 0.2f*vz + 0.8f*rz;
        // write v3 at [224,320) (vh region [256,448) dead; no read overlap)
        ws[224 + lane*3 + 0] = ux;
        ws[224 + lane*3 + 1] = uy;
        ws[224 + lane*3 + 2] = uz;
        __syncwarp();

        // ---- layer 2 (lane owns h = lane) ----
        float bx = 0.f, by = 0.f, bz = 0.f;
        #pragma unroll 8
        for (int c = 0; c < 32; c++) {
            float w = sWv12[c*32 + lane];
            bx += w * ws[224 + c*3 + 0];
            by += w * ws[224 + c*3 + 1];
            bz += w * ws[224 + c*3 + 2];
        }
        float vn2 = sqrtf(bx*bx + by*by + bz*bz);
        float partial = vn2 * sWs2[lane];
        #pragma unroll
        for (int q = 0; q < 4; q++) {
            float x = ws[lane + 32*q];
            x = (x >= 0.f) ? x : 0.01f * x;       // scalar LeakyReLU(0.01)
            partial += x * sWs2[32 + lane + 32*q];
        }
        #pragma unroll
        for (int off = 16; off > 0; off >>= 1)
            partial += __shfl_xor_sync(0xffffffffu, partial, off);
        if (lane == 0) out[m] = partial;
        __syncwarp();
    }
}

extern "C" void kernel_launch(void* const* d_in, const int* in_sizes, int n_in,
                              void* d_out, int out_size)
{
    const float* g_sca  = (const float*)d_in[0];
    const float* g_vec  = (const float*)d_in[1];
    const int*   g_idx  = (const int*)  d_in[2];
    const float* gWv11  = (const float*)d_in[3];
    const float* gWv21  = (const float*)d_in[4];
    const float* gWs1   = (const float*)d_in[5];
    const float* gWg1   = (const float*)d_in[6];
    const float* gbg1   = (const float*)d_in[7];
    const float* gWd1   = (const float*)d_in[8];
    const float* gWv12  = (const float*)d_in[9];
    // d_in[10] = Wv2_2 (unused: only scalar branch of layer 2 is returned)
    const float* gWs2   = (const float*)d_in[11];
    // d_in[12] = Wg_2, d_in[13] = bg_2 (unused)
    float* out = (float*)d_out;
    const int M = in_sizes[2];

    const int smem_bytes = SMEM_FLOATS * (int)sizeof(float);  // 230144 B
    cudaFuncSetAttribute(frontier_vn_kernel,
                         cudaFuncAttributeMaxDynamicSharedMemorySize, smem_bytes);

    int sms = 148;
    cudaDeviceGetAttribute(&sms, cudaDevAttrMultiProcessorCount, 0);

    frontier_vn_kernel<<<sms, THREADS, smem_bytes>>>(
        g_sca, g_vec, g_idx,
        gWv11, gWv21, gWs1, gWg1, gbg1, gWd1, gWv12, gWs2,
        out, M);
}

// round 3
// speedup vs baseline: 1.8643x; 1.8643x over previous
#include <cuda_runtime.h>

// ---------------------------------------------------------------------------
// FrontierLayerVN fused kernel, v3:
//   - 8 warps/SM persistent, R=4 rows per warp (register-blocked GEMV:
//     weight LDS shared across 4 rows)
//   - float4 weight loads, float4 smem broadcasts
//   - fma.rn.f32x2 packed fp32 FMAs in the vh and s1 GEMVs
//   - one 512-float per-warp smem region, time-multiplexed across phases
// ---------------------------------------------------------------------------

#define NWARPS 8
#define THREADS (NWARPS * 32)
#define FULLMASK 0xffffffffu

#define SZ_WV11 4096   // 64x64
#define SZ_WV21 2048   // 64x32
#define SZ_WS1  40960  // 320x128
#define SZ_WG1  4096   // 128x32
#define SZ_BG1  32
#define SZ_WD1  1024   // 32x32
#define SZ_WV12 1024   // 32x32
#define SZ_WS2  160
#define SZ_WEIGHTS (SZ_WV11 + SZ_WV21 + SZ_WS1 + SZ_WG1 + SZ_BG1 + SZ_WD1 + SZ_WV12 + SZ_WS2)
#define WS_FLOATS 512
#define SMEM_FLOATS (SZ_WEIGHTS + NWARPS * WS_FLOATS)   // 57536 floats = 230144 B

typedef unsigned long long u64;

__device__ __forceinline__ u64 pk2(float x, float y) {
    u64 d; asm("mov.b64 %0, {%1, %2};" : "=l"(d) : "f"(x), "f"(y)); return d;
}
__device__ __forceinline__ void upk2(float& x, float& y, u64 d) {
    asm("mov.b64 {%0, %1}, %2;" : "=f"(x), "=f"(y) : "l"(d));
}
__device__ __forceinline__ void fma2(u64& a, u64 x, u64 w) {
    asm("fma.rn.f32x2 %0, %1, %2, %3;" : "=l"(a) : "l"(x), "l"(w), "l"(a));
}
__device__ __forceinline__ float fcomp(const float4& v, int e) {
    return (&v.x)[e];   // e is compile-time under #pragma unroll
}

__global__ __launch_bounds__(THREADS, 1)
void frontier_vn_kernel(
    const float* __restrict__ g_sca,   // (N,256)
    const float* __restrict__ g_vec,   // (N,64,3)
    const int*   __restrict__ g_idx,   // (M,)
    const float* __restrict__ gWv11,   // (64,64)
    const float* __restrict__ gWv21,   // (64,32)
    const float* __restrict__ gWs1,    // (320,128)
    const float* __restrict__ gWg1,    // (128,32)
    const float* __restrict__ gbg1,    // (32,)
    const float* __restrict__ gWd1,    // (32,32)
    const float* __restrict__ gWv12,   // (32,32)
    const float* __restrict__ gWs2,    // (160,)
    float* __restrict__ out,           // (M,)
    int M)
{
    extern __shared__ float sm[];
    float* sWv11 = sm;
    float* sWv21 = sWv11 + SZ_WV11;
    float* sWs1  = sWv21 + SZ_WV21;
    float* sWg1  = sWs1  + SZ_WS1;
    float* sbg1  = sWg1  + SZ_WG1;
    float* sWd1  = sbg1  + SZ_BG1;
    float* sWv12 = sWd1  + SZ_WD1;
    float* sWs2  = sWv12 + SZ_WV12;
    float* scratch = sWs2 + SZ_WS2;

    const int tid = threadIdx.x;

    // ---- cooperative weight staging ----
    {
        const float4* s = (const float4*)0; float4* d = (float4*)0;
        d = (float4*)sWv11; s = (const float4*)gWv11;
        for (int i = tid; i < SZ_WV11/4; i += THREADS) d[i] = s[i];
        d = (float4*)sWv21; s = (const float4*)gWv21;
        for (int i = tid; i < SZ_WV21/4; i += THREADS) d[i] = s[i];
        d = (float4*)sWs1;  s = (const float4*)gWs1;
        for (int i = tid; i < SZ_WS1/4;  i += THREADS) d[i] = s[i];
        d = (float4*)sWg1;  s = (const float4*)gWg1;
        for (int i = tid; i < SZ_WG1/4;  i += THREADS) d[i] = s[i];
        d = (float4*)sbg1;  s = (const float4*)gbg1;
        for (int i = tid; i < SZ_BG1/4;  i += THREADS) d[i] = s[i];
        d = (float4*)sWd1;  s = (const float4*)gWd1;
        for (int i = tid; i < SZ_WD1/4;  i += THREADS) d[i] = s[i];
        d = (float4*)sWv12; s = (const float4*)gWv12;
        for (int i = tid; i < SZ_WV12/4; i += THREADS) d[i] = s[i];
        d = (float4*)sWs2;  s = (const float4*)gWs2;
        for (int i = tid; i < SZ_WS2/4;  i += THREADS) d[i] = s[i];
    }
    __syncthreads();

    const int warp = tid >> 5;
    const int lane = tid & 31;
    float* ws = scratch + warp * WS_FLOATS;     // 512 floats, 16B aligned
    float4* wsv4 = (float4*)ws;

    const float2* sWv11_f2 = (const float2*)sWv11;
    const float4* sWs1_f4  = (const float4*)sWs1;
    const float4* sWs2_f4  = (const float4*)sWs2;
    const float4* g_sca4   = (const float4*)g_sca;

    for (int base = (blockIdx.x * NWARPS + warp) * 4; base < M;
         base += gridDim.x * NWARPS * 4)
    {
        int idxr[4];
        #pragma unroll
        for (int r = 0; r < 4; r++) {
            int m = base + r;
            idxr[r] = g_idx[(m < M) ? m : (M - 1)];
        }

        // =================== Stage A: vec -> vh (packed per h-pair) =========
        // pax[r] = (vh[2l].x, vh[2l+1].x), etc.
        u64 pax[4], pay[4], paz[4];
        #pragma unroll
        for (int r = 0; r < 4; r++) { pax[r] = 0ull; pay[r] = 0ull; paz[r] = 0ull; }

        #pragma unroll
        for (int t = 0; t < 2; t++) {
            float va[4][3];
            #pragma unroll
            for (int r = 0; r < 4; r++) {
                const float* vp = g_vec + (size_t)idxr[r] * 192 + t * 96 + 3 * lane;
                va[r][0] = vp[0]; va[r][1] = vp[1]; va[r][2] = vp[2];
            }
            __syncwarp();   // prior-phase readers done before overwrite
            #pragma unroll
            for (int r = 0; r < 4; r++) {
                ws[r*96 + 0*32 + lane] = va[r][0];   // vec[32t+lane][i], comp-major
                ws[r*96 + 1*32 + lane] = va[r][1];
                ws[r*96 + 2*32 + lane] = va[r][2];
            }
            __syncwarp();

            for (int cq = 0; cq < 8; cq++) {
                float4 xv[4][3];
                #pragma unroll
                for (int r = 0; r < 4; r++) {
                    xv[r][0] = wsv4[r*24 + 0*8 + cq];
                    xv[r][1] = wsv4[r*24 + 1*8 + cq];
                    xv[r][2] = wsv4[r*24 + 2*8 + cq];
                }
                #pragma unroll
                for (int e = 0; e < 4; e++) {
                    int c = t*32 + cq*4 + e;
                    float2 w2 = sWv11_f2[c*32 + lane];   // (W[c][2l], W[c][2l+1])
                    u64 ww = pk2(w2.x, w2.y);
                    #pragma unroll
                    for (int r = 0; r < 4; r++) {
                        float vx = fcomp(xv[r][0], e);
                        float vy = fcomp(xv[r][1], e);
                        float vz = fcomp(xv[r][2], e);
                        fma2(pax[r], pk2(vx, vx), ww);
                        fma2(pay[r], pk2(vy, vy), ww);
                        fma2(paz[r], pk2(vz, vz), ww);
                    }
                }
            }
            __syncwarp();
        }

        // vnorm: vn0[r]=||vh[2l]||, vn1[r]=||vh[2l+1]||
        float vn0[4], vn1[4];
        #pragma unroll
        for (int r = 0; r < 4; r++) {
            float x0,x1,y0,y1,z0,z1;
            upk2(x0,x1,pax[r]); upk2(y0,y1,pay[r]); upk2(z0,z1,paz[r]);
            vn0[r] = sqrtf(x0*x0 + y0*y0 + z0*z0);
            vn1[r] = sqrtf(x1*x1 + y1*y1 + z1*z1);
        }

        // =================== Stage B: s1 (lane owns j=4l..4l+3) =============
        u64 ps01[4], ps23[4];
        #pragma unroll
        for (int r = 0; r < 4; r++) { ps01[r] = 0ull; ps23[r] = 0ull; }

        // vn part: k = h in [0,64), vn owned at lane h>>1, reg h&1
        #pragma unroll 8
        for (int k = 0; k < 64; k++) {
            float4 w = sWs1_f4[k*32 + lane];
            u64 wa = pk2(w.x, w.y), wb = pk2(w.z, w.w);
            #pragma unroll
            for (int r = 0; r < 4; r++) {
                float x = __shfl_sync(FULLMASK, (k & 1) ? vn1[r] : vn0[r], k >> 1);
                u64 xx = pk2(x, x);
                fma2(ps01[r], xx, wa);
                fma2(ps23[r], xx, wb);
            }
        }
        // sca part: chunks of 128, staged through smem
        #pragma unroll
        for (int t = 0; t < 2; t++) {
            float4 sc[4];
            #pragma unroll
            for (int r = 0; r < 4; r++)
                sc[r] = g_sca4[(size_t)idxr[r]*64 + t*32 + lane];
            __syncwarp();
            #pragma unroll
            for (int r = 0; r < 4; r++) wsv4[r*32 + lane] = sc[r];
            __syncwarp();

            for (int kq = 0; kq < 32; kq++) {
                float4 xs[4];
                #pragma unroll
                for (int r = 0; r < 4; r++) xs[r] = wsv4[r*32 + kq];
                #pragma unroll
                for (int e = 0; e < 4; e++) {
                    int k = 64 + t*128 + kq*4 + e;
                    float4 w = sWs1_f4[k*32 + lane];
                    u64 wa = pk2(w.x, w.y), wb = pk2(w.z, w.w);
                    #pragma unroll
                    for (int r = 0; r < 4; r++) {
                        float x = fcomp(xs[r], e);
                        u64 xx = pk2(x, x);
                        fma2(ps01[r], xx, wa);
                        fma2(ps23[r], xx, wb);
                    }
                }
            }
            __syncwarp();
        }

        // =================== Stage C: write s1, gate ========================
        #pragma unroll
        for (int r = 0; r < 4; r++) {
            float4 sv;
            upk2(sv.x, sv.y, ps01[r]);
            upk2(sv.z, sv.w, ps23[r]);
            wsv4[r*32 + lane] = sv;   // s1buf[r][4l..4l+3]
        }
        __syncwarp();

        float gg[4] = {0.f, 0.f, 0.f, 0.f};
        for (int jq = 0; jq < 32; jq++) {
            float4 xs[4];
            #pragma unroll
            for (int r = 0; r < 4; r++) xs[r] = wsv4[r*32 + jq];
            #pragma unroll
            for (int e = 0; e < 4; e++) {
                float w = sWg1[(jq*4 + e)*32 + lane];
                #pragma unroll
                for (int r = 0; r < 4; r++) gg[r] += fcomp(xs[r], e) * w;
            }
        }
        #pragma unroll
        for (int r = 0; r < 4; r++)
            gg[r] = 1.f / (1.f + __expf(-(gg[r] + sbg1[lane])));

        // =================== Stage D: out_vec (vh via smem chunks) ==========
        float ox[4] = {0,0,0,0}, oy[4] = {0,0,0,0}, oz[4] = {0,0,0,0};
        #pragma unroll
        for (int t = 0; t < 2; t++) {
            __syncwarp();   // gate (t=0) / chunk0 readers (t=1) done
            if ((lane >> 4) == t) {      // lanes owning h=2l,2l+1 in [32t,32t+32)
                int h0 = 2*lane - 32*t;
                #pragma unroll
                for (int r = 0; r < 4; r++) {
                    *(u64*)(ws + r*96 + 0*32 + h0) = pax[r];
                    *(u64*)(ws + r*96 + 1*32 + h0) = pay[r];
                    *(u64*)(ws + r*96 + 2*32 + h0) = paz[r];
                }
            }
            __syncwarp();
            for (int hq = 0; hq < 8; hq++) {
                float4 xv[4][3];
                #pragma unroll
                for (int r = 0; r < 4; r++) {
                    xv[r][0] = wsv4[r*24 + 0*8 + hq];
                    xv[r][1] = wsv4[r*24 + 1*8 + hq];
                    xv[r][2] = wsv4[r*24 + 2*8 + hq];
                }
                #pragma unroll
                for (int e = 0; e < 4; e++) {
                    int h = t*32 + hq*4 + e;
                    float w = sWv21[h*32 + lane];
                    #pragma unroll
                    for (int r = 0; r < 4; r++) {
                        ox[r] += w * fcomp(xv[r][0], e);
                        oy[r] += w * fcomp(xv[r][1], e);
                        oz[r] += w * fcomp(xv[r][2], e);
                    }
                }
            }
        }
        float v2x[4], v2y[4], v2z[4];
        #pragma unroll
        for (int r = 0; r < 4; r++) {
            v2x[r] = gg[r]*ox[r]; v2y[r] = gg[r]*oy[r]; v2z[r] = gg[r]*oz[r];
        }

        // =================== Stage E: VNLeakyReLU ===========================
        __syncwarp();
        #pragma unroll
        for (int r = 0; r < 4; r++) {
            ws[r*96 + 0*32 + lane] = v2x[r];
            ws[r*96 + 1*32 + lane] = v2y[r];
            ws[r*96 + 2*32 + lane] = v2z[r];
        }
        __syncwarp();
        float dx[4] = {0,0,0,0}, dy[4] = {0,0,0,0}, dz[4] = {0,0,0,0};
        for (int cq = 0; cq < 8; cq++) {
            float4 xv[4][3];
            #pragma unroll
            for (int r = 0; r < 4; r++) {
                xv[r][0] = wsv4[r*24 + 0*8 + cq];
                xv[r][1] = wsv4[r*24 + 1*8 + cq];
                xv[r][2] = wsv4[r*24 + 2*8 + cq];
            }
            #pragma unroll
            for (int e = 0; e < 4; e++) {
                float w = sWd1[(cq*4 + e)*32 + lane];
                #pragma unroll
                for (int r = 0; r < 4; r++) {
                    dx[r] += w * fcomp(xv[r][0], e);
                    dy[r] += w * fcomp(xv[r][1], e);
                    dz[r] += w * fcomp(xv[r][2], e);
                }
            }
        }
        float v3x[4], v3y[4], v3z[4];
        #pragma unroll
        for (int r = 0; r < 4; r++) {
            float dot = v2x[r]*dx[r] + v2y[r]*dy[r] + v2z[r]*dz[r];
            float dsq = dx[r]*dx[r] + dy[r]*dy[r] + dz[r]*dz[r];
            float tt  = dot / (dsq + 1e-6f);
            float rx = (dot >= 0.f) ? v2x[r] : (v2x[r] - tt*dx[r]);
            float ry = (dot >= 0.f) ? v2y[r] : (v2y[r] - tt*dy[r]);
            float rz = (dot >= 0.f) ? v2z[r] : (v2z[r] - tt*dz[r]);
            v3x[r] = 0.2f*v2x[r] + 0.8f*rx;
            v3y[r] = 0.2f*v2y[r] + 0.8f*ry;
            v3z[r] = 0.2f*v2z[r] + 0.8f*rz;
        }

        // =================== Stage F: layer 2 + output ======================
        __syncwarp();
        #pragma unroll
        for (int r = 0; r < 4; r++) {
            ws[r*96 + 0*32 + lane] = v3x[r];
            ws[r*96 + 1*32 + lane] = v3y[r];
            ws[r*96 + 2*32 + lane] = v3z[r];
        }
        __syncwarp();
        float bx[4] = {0,0,0,0}, by[4] = {0,0,0,0}, bz[4] = {0,0,0,0};
        for (int cq = 0; cq < 8; cq++) {
            float4 xv[4][3];
            #pragma unroll
            for (int r = 0; r < 4; r++) {
                xv[r][0] = wsv4[r*24 + 0*8 + cq];
                xv[r][1] = wsv4[r*24 + 1*8 + cq];
                xv[r][2] = wsv4[r*24 + 2*8 + cq];
            }
            #pragma unroll
            for (int e = 0; e < 4; e++) {
                float w = sWv12[(cq*4 + e)*32 + lane];
                #pragma unroll
                for (int r = 0; r < 4; r++) {
                    bx[r] += w * fcomp(xv[r][0], e);
                    by[r] += w * fcomp(xv[r][1], e);
                    bz[r] += w * fcomp(xv[r][2], e);
                }
            }
        }

        float w2head = sWs2[lane];
        float4 w2tail = sWs2_f4[8 + lane];   // Ws2[32+4l .. 32+4l+3]
        float part[4];
        #pragma unroll
        for (int r = 0; r < 4; r++) {
            float vn2 = sqrtf(bx[r]*bx[r] + by[r]*by[r] + bz[r]*bz[r]);
            float p = vn2 * w2head;
            float s0, s1v, s2, s3;
            upk2(s0, s1v, ps01[r]);
            upk2(s2, s3,  ps23[r]);
            p += ((s0  >= 0.f) ? s0  : 0.01f*s0)  * w2tail.x;
            p += ((s1v >= 0.f) ? s1v : 0.01f*s1v) * w2tail.y;
            p += ((s2  >= 0.f) ? s2  : 0.01f*s2)  * w2tail.z;
            p += ((s3  >= 0.f) ? s3  : 0.01f*s3)  * w2tail.w;
            #pragma unroll
            for (int off = 16; off > 0; off >>= 1)
                p += __shfl_xor_sync(FULLMASK, p, off);
            part[r] = p;
        }
        if (lane == 0) {
            #pragma unroll
            for (int r = 0; r < 4; r++) {
                int m = base + r;
                if (m < M) out[m] = part[r];
            }
        }
        __syncwarp();
    }
}

extern "C" void kernel_launch(void* const* d_in, const int* in_sizes, int n_in,
                              void* d_out, int out_size)
{
    const float* g_sca  = (const float*)d_in[0];
    const float* g_vec  = (const float*)d_in[1];
    const int*   g_idx  = (const int*)  d_in[2];
    const float* gWv11  = (const float*)d_in[3];
    const float* gWv21  = (const float*)d_in[4];
    const float* gWs1   = (const float*)d_in[5];
    const float* gWg1   = (const float*)d_in[6];
    const float* gbg1   = (const float*)d_in[7];
    const float* gWd1   = (const float*)d_in[8];
    const float* gWv12  = (const float*)d_in[9];
    const float* gWs2   = (const float*)d_in[11];
    float* out = (float*)d_out;
    const int M = in_sizes[2];

    const int smem_bytes = SMEM_FLOATS * (int)sizeof(float);  // 230144 B
    cudaFuncSetAttribute(frontier_vn_kernel,
                         cudaFuncAttributeMaxDynamicSharedMemorySize, smem_bytes);

    int sms = 148;
    cudaDeviceGetAttribute(&sms, cudaDevAttrMultiProcessorCount, 0);

    frontier_vn_kernel<<<sms, THREADS, smem_bytes>>>(
        g_sca, g_vec, g_idx,
        gWv11, gWv21, gWs1, gWg1, gbg1, gWd1, gWv12, gWs2,
        out, M);
}

// round 4
// speedup vs baseline: 1.8783x; 1.0075x over previous
#include <cuda_runtime.h>

// ---------------------------------------------------------------------------
// FrontierLayerVN fused kernel, v4:
//   - 8 warps/SM persistent, R=8 rows per warp for the big Ws1 GEMV
//     (weight LDS shared across 8 rows), other stages run as 2x 4-row passes
//   - fma.rn.f32x2 packing everywhere: j-pairs (Ws1), row-pairs (gate),
//     component-pairs (Wv21/Wd1/Wv12)
//   - one 512-float per-warp smem region, time-multiplexed
// ---------------------------------------------------------------------------

#define NWARPS 8
#define THREADS (NWARPS * 32)
#define FULLMASK 0xffffffffu

#define SZ_WV11 4096   // 64x64
#define SZ_WV21 2048   // 64x32
#define SZ_WS1  40960  // 320x128
#define SZ_WG1  4096   // 128x32
#define SZ_BG1  32
#define SZ_WD1  1024   // 32x32
#define SZ_WV12 1024   // 32x32
#define SZ_WS2  160
#define SZ_WEIGHTS (SZ_WV11 + SZ_WV21 + SZ_WS1 + SZ_WG1 + SZ_BG1 + SZ_WD1 + SZ_WV12 + SZ_WS2)
#define WS_FLOATS 512
#define SMEM_FLOATS (SZ_WEIGHTS + NWARPS * WS_FLOATS)   // 230144 B

typedef unsigned long long u64;

__device__ __forceinline__ u64 pk2(float x, float y) {
    u64 d; asm("mov.b64 %0, {%1, %2};" : "=l"(d) : "f"(x), "f"(y)); return d;
}
__device__ __forceinline__ void upk2(float& x, float& y, u64 d) {
    asm("mov.b64 {%0, %1}, %2;" : "=f"(x), "=f"(y) : "l"(d));
}
__device__ __forceinline__ void fma2(u64& a, u64 x, u64 w) {
    asm("fma.rn.f32x2 %0, %1, %2, %3;" : "=l"(a) : "l"(x), "l"(w), "l"(a));
}
__device__ __forceinline__ float fcomp(const float4& v, int e) {
    return (&v.x)[e];   // e compile-time under #pragma unroll
}

__global__ __launch_bounds__(THREADS, 1)
void frontier_vn_kernel(
    const float* __restrict__ g_sca,   // (N,256)
    const float* __restrict__ g_vec,   // (N,64,3)
    const int*   __restrict__ g_idx,   // (M,)
    const float* __restrict__ gWv11,   // (64,64)
    const float* __restrict__ gWv21,   // (64,32)
    const float* __restrict__ gWs1,    // (320,128)
    const float* __restrict__ gWg1,    // (128,32)
    const float* __restrict__ gbg1,    // (32,)
    const float* __restrict__ gWd1,    // (32,32)
    const float* __restrict__ gWv12,   // (32,32)
    const float* __restrict__ gWs2,    // (160,)
    float* __restrict__ out,           // (M,)
    int M)
{
    extern __shared__ float sm[];
    float* sWv11 = sm;
    float* sWv21 = sWv11 + SZ_WV11;
    float* sWs1  = sWv21 + SZ_WV21;
    float* sWg1  = sWs1  + SZ_WS1;
    float* sbg1  = sWg1  + SZ_WG1;
    float* sWd1  = sbg1  + SZ_BG1;
    float* sWv12 = sWd1  + SZ_WD1;
    float* sWs2  = sWv12 + SZ_WV12;
    float* scratch = sWs2 + SZ_WS2;

    const int tid = threadIdx.x;

    // ---- cooperative weight staging ----
    {
        const float4* s; float4* d;
        d = (float4*)sWv11; s = (const float4*)gWv11;
        for (int i = tid; i < SZ_WV11/4; i += THREADS) d[i] = s[i];
        d = (float4*)sWv21; s = (const float4*)gWv21;
        for (int i = tid; i < SZ_WV21/4; i += THREADS) d[i] = s[i];
        d = (float4*)sWs1;  s = (const float4*)gWs1;
        for (int i = tid; i < SZ_WS1/4;  i += THREADS) d[i] = s[i];
        d = (float4*)sWg1;  s = (const float4*)gWg1;
        for (int i = tid; i < SZ_WG1/4;  i += THREADS) d[i] = s[i];
        d = (float4*)sbg1;  s = (const float4*)gbg1;
        for (int i = tid; i < SZ_BG1/4;  i += THREADS) d[i] = s[i];
        d = (float4*)sWd1;  s = (const float4*)gWd1;
        for (int i = tid; i < SZ_WD1/4;  i += THREADS) d[i] = s[i];
        d = (float4*)sWv12; s = (const float4*)gWv12;
        for (int i = tid; i < SZ_WV12/4; i += THREADS) d[i] = s[i];
        d = (float4*)sWs2;  s = (const float4*)gWs2;
        for (int i = tid; i < SZ_WS2/4;  i += THREADS) d[i] = s[i];
    }
    __syncthreads();

    const int warp = tid >> 5;
    const int lane = tid & 31;
    float* ws = scratch + warp * WS_FLOATS;
    float4* wsv4 = (float4*)ws;

    const float2* sWv11_f2 = (const float2*)sWv11;
    const float4* sWs1_f4  = (const float4*)sWs1;
    const float4* sWs2_f4  = (const float4*)sWs2;
    const float4* g_sca4   = (const float4*)g_sca;

    for (int base = (blockIdx.x * NWARPS + warp) * 8; base < M;
         base += gridDim.x * NWARPS * 8)
    {
        int idxr[8];
        #pragma unroll
        for (int r = 0; r < 8; r++) {
            int m = base + r;
            idxr[r] = g_idx[(m < M) ? m : (M - 1)];
        }
        // per-lane dynamic row index (for sca gather: lane handles row lane>>2)
        int m_dyn = base + (lane >> 2);
        const int idx_dyn = g_idx[(m_dyn < M) ? m_dyn : (M - 1)];

        // =================== Stage A: vec -> vh, vn (2x 4-row passes) =======
        u64 pax[8], pay[8], paz[8];
        float vn0[8], vn1[8];
        #pragma unroll
        for (int p = 0; p < 2; p++) {
            #pragma unroll
            for (int r2 = 0; r2 < 4; r2++) {
                pax[p*4+r2] = 0ull; pay[p*4+r2] = 0ull; paz[p*4+r2] = 0ull;
            }
            #pragma unroll
            for (int t = 0; t < 2; t++) {
                float va[4][3];
                #pragma unroll
                for (int r2 = 0; r2 < 4; r2++) {
                    const float* vp = g_vec + (size_t)idxr[p*4+r2]*192 + t*96 + 3*lane;
                    va[r2][0] = vp[0]; va[r2][1] = vp[1]; va[r2][2] = vp[2];
                }
                __syncwarp();
                #pragma unroll
                for (int r2 = 0; r2 < 4; r2++) {
                    ws[r2*96 + 0*32 + lane] = va[r2][0];
                    ws[r2*96 + 1*32 + lane] = va[r2][1];
                    ws[r2*96 + 2*32 + lane] = va[r2][2];
                }
                __syncwarp();
                for (int cq = 0; cq < 8; cq++) {
                    float4 xv[4][3];
                    #pragma unroll
                    for (int r2 = 0; r2 < 4; r2++) {
                        xv[r2][0] = wsv4[r2*24 + 0*8 + cq];
                        xv[r2][1] = wsv4[r2*24 + 1*8 + cq];
                        xv[r2][2] = wsv4[r2*24 + 2*8 + cq];
                    }
                    #pragma unroll
                    for (int e = 0; e < 4; e++) {
                        int c = t*32 + cq*4 + e;
                        float2 w2 = sWv11_f2[c*32 + lane];   // (W[c][2l], W[c][2l+1])
                        u64 ww = pk2(w2.x, w2.y);
                        #pragma unroll
                        for (int r2 = 0; r2 < 4; r2++) {
                            float vx = fcomp(xv[r2][0], e);
                            float vy = fcomp(xv[r2][1], e);
                            float vz = fcomp(xv[r2][2], e);
                            fma2(pax[p*4+r2], pk2(vx, vx), ww);
                            fma2(pay[p*4+r2], pk2(vy, vy), ww);
                            fma2(paz[p*4+r2], pk2(vz, vz), ww);
                        }
                    }
                }
                __syncwarp();
            }
            #pragma unroll
            for (int r2 = 0; r2 < 4; r2++) {
                float x0,x1,y0,y1,z0,z1;
                upk2(x0,x1,pax[p*4+r2]); upk2(y0,y1,pay[p*4+r2]); upk2(z0,z1,paz[p*4+r2]);
                vn0[p*4+r2] = sqrtf(x0*x0 + y0*y0 + z0*z0);
                vn1[p*4+r2] = sqrtf(x1*x1 + y1*y1 + z1*z1);
            }
        }

        // =================== Stage B: s1 (lane owns j=4l..4l+3, R=8) ========
        u64 ps01[8], ps23[8];
        #pragma unroll
        for (int r = 0; r < 8; r++) { ps01[r] = 0ull; ps23[r] = 0ull; }

        // vn part: k=h in [0,64); vn for h at lane h>>1, slot h&1
        #pragma unroll 4
        for (int k = 0; k < 64; k++) {
            float4 w = sWs1_f4[k*32 + lane];
            u64 wa = pk2(w.x, w.y), wb = pk2(w.z, w.w);
            #pragma unroll
            for (int r = 0; r < 8; r++) {
                float xsrc = (k & 1) ? vn1[r] : vn0[r];
                float x = __shfl_sync(FULLMASK, xsrc, k >> 1);
                u64 xx = pk2(x, x);
                fma2(ps01[r], xx, wa);
                fma2(ps23[r], xx, wb);
            }
        }

        // sca part: 4 passes of 64 k-values, staged 8 rows x 64 = 512 floats
        for (int pass = 0; pass < 4; pass++) {
            const int rq = lane >> 2, q = lane & 3;
            float4 sc[4];
            #pragma unroll
            for (int j = 0; j < 4; j++)
                sc[j] = g_sca4[(size_t)idx_dyn*64 + pass*16 + j*4 + q];
            __syncwarp();
            #pragma unroll
            for (int j = 0; j < 4; j++)
                wsv4[rq*16 + j*4 + q] = sc[j];
            __syncwarp();

            for (int kq = 0; kq < 16; kq++) {
                float4 xs[8];
                #pragma unroll
                for (int r = 0; r < 8; r++) xs[r] = wsv4[r*16 + kq];
                #pragma unroll
                for (int e = 0; e < 4; e++) {
                    int k = 64 + pass*64 + kq*4 + e;
                    float4 w = sWs1_f4[k*32 + lane];
                    u64 wa = pk2(w.x, w.y), wb = pk2(w.z, w.w);
                    #pragma unroll
                    for (int r = 0; r < 8; r++) {
                        float x = fcomp(xs[r], e);
                        u64 xx = pk2(x, x);
                        fma2(ps01[r], xx, wa);
                        fma2(ps23[r], xx, wb);
                    }
                }
            }
            __syncwarp();
        }

        // =================== Stage C: gate (2x 4-row passes, row-pair pk) ===
        float gg[8];
        #pragma unroll
        for (int p = 0; p < 2; p++) {
            __syncwarp();
            #pragma unroll
            for (int r2 = 0; r2 < 4; r2++) {
                float4 sv;
                upk2(sv.x, sv.y, ps01[p*4+r2]);
                upk2(sv.z, sv.w, ps23[p*4+r2]);
                wsv4[r2*32 + lane] = sv;
            }
            __syncwarp();
            u64 g01 = 0ull, g23 = 0ull;
            for (int jq = 0; jq < 32; jq++) {
                float4 x0 = wsv4[0*32 + jq];
                float4 x1 = wsv4[1*32 + jq];
                float4 x2 = wsv4[2*32 + jq];
                float4 x3 = wsv4[3*32 + jq];
                #pragma unroll
                for (int e = 0; e < 4; e++) {
                    float w = sWg1[(jq*4 + e)*32 + lane];
                    u64 ww = pk2(w, w);
                    fma2(g01, pk2(fcomp(x0,e), fcomp(x1,e)), ww);
                    fma2(g23, pk2(fcomp(x2,e), fcomp(x3,e)), ww);
                }
            }
            float a,b,c,d;
            upk2(a,b,g01); upk2(c,d,g23);
            float bias = sbg1[lane];
            gg[p*4+0] = 1.f / (1.f + __expf(-(a + bias)));
            gg[p*4+1] = 1.f / (1.f + __expf(-(b + bias)));
            gg[p*4+2] = 1.f / (1.f + __expf(-(c + bias)));
            gg[p*4+3] = 1.f / (1.f + __expf(-(d + bias)));
        }

        // =================== Stage D: out_vec + gate mul (2x 4-row) =========
        float v2x[8], v2y[8], v2z[8];
        #pragma unroll
        for (int p = 0; p < 2; p++) {
            u64 oxy[4] = {0ull,0ull,0ull,0ull};
            float ozv[4] = {0.f,0.f,0.f,0.f};
            #pragma unroll
            for (int t = 0; t < 2; t++) {
                __syncwarp();
                if ((lane >> 4) == t) {
                    int h0 = 2*lane - 32*t;
                    #pragma unroll
                    for (int r2 = 0; r2 < 4; r2++) {
                        *(u64*)(ws + r2*96 + 0*32 + h0) = pax[p*4+r2];
                        *(u64*)(ws + r2*96 + 1*32 + h0) = pay[p*4+r2];
                        *(u64*)(ws + r2*96 + 2*32 + h0) = paz[p*4+r2];
                    }
                }
                __syncwarp();
                for (int hq = 0; hq < 8; hq++) {
                    float4 xv[4][3];
                    #pragma unroll
                    for (int r2 = 0; r2 < 4; r2++) {
                        xv[r2][0] = wsv4[r2*24 + 0*8 + hq];
                        xv[r2][1] = wsv4[r2*24 + 1*8 + hq];
                        xv[r2][2] = wsv4[r2*24 + 2*8 + hq];
                    }
                    #pragma unroll
                    for (int e = 0; e < 4; e++) {
                        int h = t*32 + hq*4 + e;
                        float w = sWv21[h*32 + lane];
                        u64 ww = pk2(w, w);
                        #pragma unroll
                        for (int r2 = 0; r2 < 4; r2++) {
                            fma2(oxy[r2], pk2(fcomp(xv[r2][0],e), fcomp(xv[r2][1],e)), ww);
                            ozv[r2] += w * fcomp(xv[r2][2], e);
                        }
                    }
                }
            }
            #pragma unroll
            for (int r2 = 0; r2 < 4; r2++) {
                float ox, oy; upk2(ox, oy, oxy[r2]);
                float g = gg[p*4+r2];
                v2x[p*4+r2] = g * ox;
                v2y[p*4+r2] = g * oy;
                v2z[p*4+r2] = g * ozv[r2];
            }
        }

        // =================== Stage E: VNLeakyReLU (2x 4-row) ================
        float v3x[8], v3y[8], v3z[8];
        #pragma unroll
        for (int p = 0; p < 2; p++) {
            __syncwarp();
            #pragma unroll
            for (int r2 = 0; r2 < 4; r2++) {
                ws[r2*96 + 0*32 + lane] = v2x[p*4+r2];
                ws[r2*96 + 1*32 + lane] = v2y[p*4+r2];
                ws[r2*96 + 2*32 + lane] = v2z[p*4+r2];
            }
            __syncwarp();
            u64 dxy[4] = {0ull,0ull,0ull,0ull};
            float dzv[4] = {0.f,0.f,0.f,0.f};
            for (int cq = 0; cq < 8; cq++) {
                float4 xv[4][3];
                #pragma unroll
                for (int r2 = 0; r2 < 4; r2++) {
                    xv[r2][0] = wsv4[r2*24 + 0*8 + cq];
                    xv[r2][1] = wsv4[r2*24 + 1*8 + cq];
                    xv[r2][2] = wsv4[r2*24 + 2*8 + cq];
                }
                #pragma unroll
                for (int e = 0; e < 4; e++) {
                    float w = sWd1[(cq*4 + e)*32 + lane];
                    u64 ww = pk2(w, w);
                    #pragma unroll
                    for (int r2 = 0; r2 < 4; r2++) {
                        fma2(dxy[r2], pk2(fcomp(xv[r2][0],e), fcomp(xv[r2][1],e)), ww);
                        dzv[r2] += w * fcomp(xv[r2][2], e);
                    }
                }
            }
            #pragma unroll
            for (int r2 = 0; r2 < 4; r2++) {
                int r = p*4 + r2;
                float dx, dy; upk2(dx, dy, dxy[r2]);
                float dz = dzv[r2];
                float dot = v2x[r]*dx + v2y[r]*dy + v2z[r]*dz;
                float dsq = dx*dx + dy*dy + dz*dz;
                float tt  = dot / (dsq + 1e-6f);
                float rx = (dot >= 0.f) ? v2x[r] : (v2x[r] - tt*dx);
                float ry = (dot >= 0.f) ? v2y[r] : (v2y[r] - tt*dy);
                float rz = (dot >= 0.f) ? v2z[r] : (v2z[r] - tt*dz);
                v3x[r] = 0.2f*v2x[r] + 0.8f*rx;
                v3y[r] = 0.2f*v2y[r] + 0.8f*ry;
                v3z[r] = 0.2f*v2z[r] + 0.8f*rz;
            }
        }

        // =================== Stage F: layer 2 + output (2x 4-row) ===========
        float part[8];
        float w2head = sWs2[lane];
        float4 w2tail = sWs2_f4[8 + lane];
        #pragma unroll
        for (int p = 0; p < 2; p++) {
            __syncwarp();
            #pragma unroll
            for (int r2 = 0; r2 < 4; r2++) {
                ws[r2*96 + 0*32 + lane] = v3x[p*4+r2];
                ws[r2*96 + 1*32 + lane] = v3y[p*4+r2];
                ws[r2*96 + 2*32 + lane] = v3z[p*4+r2];
            }
            __syncwarp();
            u64 bxy[4] = {0ull,0ull,0ull,0ull};
            float bzv[4] = {0.f,0.f,0.f,0.f};
            for (int cq = 0; cq < 8; cq++) {
                float4 xv[4][3];
                #pragma unroll
                for (int r2 = 0; r2 < 4; r2++) {
                    xv[r2][0] = wsv4[r2*24 + 0*8 + cq];
                    xv[r2][1] = wsv4[r2*24 + 1*8 + cq];
                    xv[r2][2] = wsv4[r2*24 + 2*8 + cq];
                }
                #pragma unroll
                for (int e = 0; e < 4; e++) {
                    float w = sWv12[(cq*4 + e)*32 + lane];
                    u64 ww = pk2(w, w);
                    #pragma unroll
                    for (int r2 = 0; r2 < 4; r2++) {
                        fma2(bxy[r2], pk2(fcomp(xv[r2][0],e), fcomp(xv[r2][1],e)), ww);
                        bzv[r2] += w * fcomp(xv[r2][2], e);
                    }
                }
            }
            #pragma unroll
            for (int r2 = 0; r2 < 4; r2++) {
                int r = p*4 + r2;
                float bx, by; upk2(bx, by, bxy[r2]);
                float bz = bzv[r2];
                float vn2 = sqrtf(bx*bx + by*by + bz*bz);
                float pp = vn2 * w2head;
                float s0, s1v, s2, s3;
                upk2(s0, s1v, ps01[r]);
                upk2(s2, s3,  ps23[r]);
                pp += ((s0  >= 0.f) ? s0  : 0.01f*s0)  * w2tail.x;
                pp += ((s1v >= 0.f) ? s1v : 0.01f*s1v) * w2tail.y;
                pp += ((s2  >= 0.f) ? s2  : 0.01f*s2)  * w2tail.z;
                pp += ((s3  >= 0.f) ? s3  : 0.01f*s3)  * w2tail.w;
                #pragma unroll
                for (int off = 16; off > 0; off >>= 1)
                    pp += __shfl_xor_sync(FULLMASK, pp, off);
                part[r] = pp;
            }
        }
        if (lane == 0) {
            #pragma unroll
            for (int r = 0; r < 8; r++) {
                int m = base + r;
                if (m < M) out[m] = part[r];
            }
        }
        __syncwarp();
    }
}

extern "C" void kernel_launch(void* const* d_in, const int* in_sizes, int n_in,
                              void* d_out, int out_size)
{
    const float* g_sca  = (const float*)d_in[0];
    const float* g_vec  = (const float*)d_in[1];
    const int*   g_idx  = (const int*)  d_in[2];
    const float* gWv11  = (const float*)d_in[3];
    const float* gWv21  = (const float*)d_in[4];
    const float* gWs1   = (const float*)d_in[5];
    const float* gWg1   = (const float*)d_in[6];
    const float* gbg1   = (const float*)d_in[7];
    const float* gWd1   = (const float*)d_in[8];
    const float* gWv12  = (const float*)d_in[9];
    const float* gWs2   = (const float*)d_in[11];
    float* out = (float*)d_out;
    const int M = in_sizes[2];

    const int smem_bytes = SMEM_FLOATS * (int)sizeof(float);  // 230144 B
    cudaFuncSetAttribute(frontier_vn_kernel,
                         cudaFuncAttributeMaxDynamicSharedMemorySize, smem_bytes);

    int sms = 148;
    cudaDeviceGetAttribute(&sms, cudaDevAttrMultiProcessorCount, 0);

    frontier_vn_kernel<<<sms, THREADS, smem_bytes>>>(
        g_sca, g_vec, g_idx,
        gWv11, gWv21, gWs1, gWg1, gbg1, gWd1, gWv12, gWs2,
        out, M);
}

// round 5
// speedup vs baseline: 2.3149x; 1.2324x over previous
#include <cuda_runtime.h>

// ---------------------------------------------------------------------------
// FrontierLayerVN fused kernel, v5:
//   - 12 warps/SM persistent (3/SMSP), R=8 rows per warp
//   - stage A single-pass (Wv11 read once per 8 rows)
//   - stage B: 10 uniform smem-staged passes (no shuffles), LDG prefetch
//   - ps registers retired right after gate (leaky-s1 dot pre-folded)
//   - D/E/F fused per 4-row half to shrink live register state
//   - scratch 384 floats/warp; smem total 232192 B
// ---------------------------------------------------------------------------

#define NWARPS 12
#define THREADS (NWARPS * 32)
#define FULLMASK 0xffffffffu

#define SZ_WV11 4096   // 64x64
#define SZ_WV21 2048   // 64x32
#define SZ_WS1  40960  // 320x128
#define SZ_WG1  4096   // 128x32
#define SZ_BG1  32
#define SZ_WD1  1024   // 32x32
#define SZ_WV12 1024   // 32x32
#define SZ_WS2  160
#define SZ_WEIGHTS (SZ_WV11 + SZ_WV21 + SZ_WS1 + SZ_WG1 + SZ_BG1 + SZ_WD1 + SZ_WV12 + SZ_WS2)
#define WS_FLOATS 384
#define SMEM_FLOATS (SZ_WEIGHTS + NWARPS * WS_FLOATS)   // 58048 floats = 232192 B

typedef unsigned long long u64;

__device__ __forceinline__ u64 pk2(float x, float y) {
    u64 d; asm("mov.b64 %0, {%1, %2};" : "=l"(d) : "f"(x), "f"(y)); return d;
}
__device__ __forceinline__ void upk2(float& x, float& y, u64 d) {
    asm("mov.b64 {%0, %1}, %2;" : "=f"(x), "=f"(y) : "l"(d));
}
__device__ __forceinline__ void fma2(u64& a, u64 x, u64 w) {
    asm("fma.rn.f32x2 %0, %1, %2, %3;" : "=l"(a) : "l"(x), "l"(w), "l"(a));
}
__device__ __forceinline__ float fcomp(const float4& v, int e) {
    return (&v.x)[e];   // e compile-time under #pragma unroll
}

// stage-B inner k-loop over a staged 32-k chunk (layout [r][32] floats)
__device__ __forceinline__ void b_chunk(
    u64* __restrict__ ps01, u64* __restrict__ ps23,
    const float4* __restrict__ wsv4, const float4* __restrict__ sWs1_f4,
    int k_base, int lane)
{
    for (int kq = 0; kq < 8; kq++) {
        float4 xs[8];
        #pragma unroll
        for (int r = 0; r < 8; r++) xs[r] = wsv4[r*8 + kq];
        #pragma unroll
        for (int e = 0; e < 4; e++) {
            int k = k_base + kq*4 + e;
            float4 w = sWs1_f4[k*32 + lane];
            u64 wa = pk2(w.x, w.y), wb = pk2(w.z, w.w);
            #pragma unroll
            for (int r = 0; r < 8; r++) {
                float x = fcomp(xs[r], e);
                u64 xx = pk2(x, x);
                fma2(ps01[r], xx, wa);
                fma2(ps23[r], xx, wb);
            }
        }
    }
}

__global__ __launch_bounds__(THREADS, 1)
void frontier_vn_kernel(
    const float* __restrict__ g_sca,   // (N,256)
    const float* __restrict__ g_vec,   // (N,64,3)
    const int*   __restrict__ g_idx,   // (M,)
    const float* __restrict__ gWv11,   // (64,64)
    const float* __restrict__ gWv21,   // (64,32)
    const float* __restrict__ gWs1,    // (320,128)
    const float* __restrict__ gWg1,    // (128,32)
    const float* __restrict__ gbg1,    // (32,)
    const float* __restrict__ gWd1,    // (32,32)
    const float* __restrict__ gWv12,   // (32,32)
    const float* __restrict__ gWs2,    // (160,)
    float* __restrict__ out,           // (M,)
    int M)
{
    extern __shared__ float sm[];
    float* sWv11 = sm;
    float* sWv21 = sWv11 + SZ_WV11;
    float* sWs1  = sWv21 + SZ_WV21;
    float* sWg1  = sWs1  + SZ_WS1;
    float* sbg1  = sWg1  + SZ_WG1;
    float* sWd1  = sbg1  + SZ_BG1;
    float* sWv12 = sWd1  + SZ_WD1;
    float* sWs2  = sWv12 + SZ_WV12;
    float* scratch = sWs2 + SZ_WS2;

    const int tid = threadIdx.x;

    // ---- cooperative weight staging ----
    {
        const float4* s; float4* d;
        d = (float4*)sWv11; s = (const float4*)gWv11;
        for (int i = tid; i < SZ_WV11/4; i += THREADS) d[i] = s[i];
        d = (float4*)sWv21; s = (const float4*)gWv21;
        for (int i = tid; i < SZ_WV21/4; i += THREADS) d[i] = s[i];
        d = (float4*)sWs1;  s = (const float4*)gWs1;
        for (int i = tid; i < SZ_WS1/4;  i += THREADS) d[i] = s[i];
        d = (float4*)sWg1;  s = (const float4*)gWg1;
        for (int i = tid; i < SZ_WG1/4;  i += THREADS) d[i] = s[i];
        d = (float4*)sbg1;  s = (const float4*)gbg1;
        for (int i = tid; i < SZ_BG1/4;  i += THREADS) d[i] = s[i];
        d = (float4*)sWd1;  s = (const float4*)gWd1;
        for (int i = tid; i < SZ_WD1/4;  i += THREADS) d[i] = s[i];
        d = (float4*)sWv12; s = (const float4*)gWv12;
        for (int i = tid; i < SZ_WV12/4; i += THREADS) d[i] = s[i];
        d = (float4*)sWs2;  s = (const float4*)gWs2;
        for (int i = tid; i < SZ_WS2/4;  i += THREADS) d[i] = s[i];
    }
    __syncthreads();

    const int warp = tid >> 5;
    const int lane = tid & 31;
    float* ws = scratch + warp * WS_FLOATS;
    float4* wsv4 = (float4*)ws;

    const float2* sWv11_f2 = (const float2*)sWv11;
    const float4* sWs1_f4  = (const float4*)sWs1;
    const float4* sWs2_f4  = (const float4*)sWs2;
    const float4* g_sca4   = (const float4*)g_sca;
    const float4* g_vec4   = (const float4*)g_vec;

    const int r_ln = lane >> 2;      // row handled by this lane in gathers
    const int q_ln = lane & 3;

    for (int base = (blockIdx.x * NWARPS + warp) * 8; base < M;
         base += gridDim.x * NWARPS * 8)
    {
        int m_dyn = base + r_ln;
        const int idx_dyn = g_idx[(m_dyn < M) ? m_dyn : (M - 1)];
        const size_t vbase = (size_t)idx_dyn * 48;   // f4 units
        const size_t sbase = (size_t)idx_dyn * 64;   // f4 units

        // =================== Stage A: vec -> vh (single pass, R=8) ==========
        u64 pax[8], pay[8], paz[8];
        #pragma unroll
        for (int r = 0; r < 8; r++) { pax[r]=0ull; pay[r]=0ull; paz[r]=0ull; }

        float4 vf0 = g_vec4[vbase + 3*q_ln + 0];
        float4 vf1 = g_vec4[vbase + 3*q_ln + 1];
        float4 vf2 = g_vec4[vbase + 3*q_ln + 2];

        for (int chunk = 0; chunk < 4; chunk++) {
            __syncwarp();
            wsv4[r_ln*12 + 3*q_ln + 0] = vf0;
            wsv4[r_ln*12 + 3*q_ln + 1] = vf1;
            wsv4[r_ln*12 + 3*q_ln + 2] = vf2;
            if (chunk < 3) {
                vf0 = g_vec4[vbase + (chunk+1)*12 + 3*q_ln + 0];
                vf1 = g_vec4[vbase + (chunk+1)*12 + 3*q_ln + 1];
                vf2 = g_vec4[vbase + (chunk+1)*12 + 3*q_ln + 2];
            }
            __syncwarp();
            for (int cq = 0; cq < 4; cq++) {
                u64 ww[4];
                #pragma unroll
                for (int e = 0; e < 4; e++) {
                    float2 w2 = sWv11_f2[(chunk*16 + cq*4 + e)*32 + lane];
                    ww[e] = pk2(w2.x, w2.y);
                }
                #pragma unroll
                for (int r = 0; r < 8; r++) {
                    float4 f0 = wsv4[r*12 + 3*cq + 0];
                    float4 f1 = wsv4[r*12 + 3*cq + 1];
                    float4 f2 = wsv4[r*12 + 3*cq + 2];
                    float vcx[4] = {f0.x, f0.w, f1.z, f2.y};
                    float vcy[4] = {f0.y, f1.x, f1.w, f2.z};
                    float vcz[4] = {f0.z, f1.y, f2.x, f2.w};
                    #pragma unroll
                    for (int e = 0; e < 4; e++) {
                        fma2(pax[r], pk2(vcx[e], vcx[e]), ww[e]);
                        fma2(pay[r], pk2(vcy[e], vcy[e]), ww[e]);
                        fma2(paz[r], pk2(vcz[e], vcz[e]), ww[e]);
                    }
                }
            }
        }

        // =================== Stage B: s1 (10 staged passes, no shuffles) ====
        u64 ps01[8], ps23[8];
        #pragma unroll
        for (int r = 0; r < 8; r++) { ps01[r]=0ull; ps23[r]=0ull; }

        // prefetch first sca chunk
        float4 sf0 = g_sca4[sbase + q_ln];
        float4 sf1 = g_sca4[sbase + q_ln + 4];

        // vn passes: k in [0,64), two 32-k chunks; norms computed inline
        #pragma unroll
        for (int chunk = 0; chunk < 2; chunk++) {
            __syncwarp();
            if ((lane >> 4) == chunk) {
                int klocal = 2*lane - 32*chunk;   // even, 0..30
                #pragma unroll
                for (int r = 0; r < 8; r++) {
                    float x0,x1,y0,y1,z0,z1;
                    upk2(x0,x1,pax[r]); upk2(y0,y1,pay[r]); upk2(z0,z1,paz[r]);
                    float2 nn;
                    nn.x = sqrtf(x0*x0 + y0*y0 + z0*z0);
                    nn.y = sqrtf(x1*x1 + y1*y1 + z1*z1);
                    *(float2*)(ws + r*32 + klocal) = nn;
                }
            }
            __syncwarp();
            b_chunk(ps01, ps23, wsv4, sWs1_f4, chunk*32, lane);
        }

        // sca passes: k in [64,320), eight 32-k chunks, prefetched
        for (int pass = 0; pass < 8; pass++) {
            __syncwarp();
            wsv4[r_ln*8 + q_ln]     = sf0;
            wsv4[r_ln*8 + q_ln + 4] = sf1;
            if (pass < 7) {
                sf0 = g_sca4[sbase + (pass+1)*8 + q_ln];
                sf1 = g_sca4[sbase + (pass+1)*8 + q_ln + 4];
            }
            __syncwarp();
            b_chunk(ps01, ps23, wsv4, sWs1_f4, 64 + pass*32, lane);
        }

        // =================== Stage C: gate (2x 4-row passes, j-halves) ======
        float gg[8];
        #pragma unroll
        for (int p = 0; p < 2; p++) {
            u64 g01 = 0ull, g23 = 0ull;
            #pragma unroll
            for (int half = 0; half < 2; half++) {
                __syncwarp();
                if ((lane >> 4) == half) {
                    int jl = lane & 15;
                    #pragma unroll
                    for (int r2 = 0; r2 < 4; r2++) {
                        float4 sv;
                        upk2(sv.x, sv.y, ps01[p*4+r2]);
                        upk2(sv.z, sv.w, ps23[p*4+r2]);
                        wsv4[r2*16 + jl] = sv;
                    }
                }
                __syncwarp();
                for (int jq = 0; jq < 16; jq++) {
                    float4 x0 = wsv4[0*16 + jq];
                    float4 x1 = wsv4[1*16 + jq];
                    float4 x2 = wsv4[2*16 + jq];
                    float4 x3 = wsv4[3*16 + jq];
                    #pragma unroll
                    for (int e = 0; e < 4; e++) {
                        float w = sWg1[(half*64 + jq*4 + e)*32 + lane];
                        u64 ww = pk2(w, w);
                        fma2(g01, pk2(fcomp(x0,e), fcomp(x1,e)), ww);
                        fma2(g23, pk2(fcomp(x2,e), fcomp(x3,e)), ww);
                    }
                }
            }
            float a,b,c,d;
            upk2(a,b,g01); upk2(c,d,g23);
            float bias = sbg1[lane];
            gg[p*4+0] = 1.f / (1.f + __expf(-(a + bias)));
            gg[p*4+1] = 1.f / (1.f + __expf(-(b + bias)));
            gg[p*4+2] = 1.f / (1.f + __expf(-(c + bias)));
            gg[p*4+3] = 1.f / (1.f + __expf(-(d + bias)));
        }

        // retire ps: fold leaky(s1) . Ws2_tail into per-lane partials
        float partB[8];
        {
            float4 w2tail = sWs2_f4[8 + lane];
            #pragma unroll
            for (int r = 0; r < 8; r++) {
                float s0,s1v,s2,s3;
                upk2(s0,s1v,ps01[r]); upk2(s2,s3,ps23[r]);
                float p = ((s0  >= 0.f) ? s0  : 0.01f*s0)  * w2tail.x;
                p      += ((s1v >= 0.f) ? s1v : 0.01f*s1v) * w2tail.y;
                p      += ((s2  >= 0.f) ? s2  : 0.01f*s2)  * w2tail.z;
                p      += ((s3  >= 0.f) ? s3  : 0.01f*s3)  * w2tail.w;
                partB[r] = p;
            }
        }

        // =================== Stages D/E/F fused per 4-row half ==============
        float w2head = sWs2[lane];
        #pragma unroll
        for (int p = 0; p < 2; p++) {
            // ---- D: out_vec ----
            u64 oxy[4] = {0ull,0ull,0ull,0ull};
            float ozv[4] = {0.f,0.f,0.f,0.f};
            #pragma unroll
            for (int t = 0; t < 2; t++) {
                __syncwarp();
                if ((lane >> 4) == t) {
                    int h0 = 2*lane - 32*t;
                    #pragma unroll
                    for (int r2 = 0; r2 < 4; r2++) {
                        *(u64*)(ws + r2*96 +  0 + h0) = pax[p*4+r2];
                        *(u64*)(ws + r2*96 + 32 + h0) = pay[p*4+r2];
                        *(u64*)(ws + r2*96 + 64 + h0) = paz[p*4+r2];
                    }
                }
                __syncwarp();
                for (int hq = 0; hq < 8; hq++) {
                    float4 xv[4][3];
                    #pragma unroll
                    for (int r2 = 0; r2 < 4; r2++) {
                        xv[r2][0] = wsv4[r2*24 + 0*8 + hq];
                        xv[r2][1] = wsv4[r2*24 + 1*8 + hq];
                        xv[r2][2] = wsv4[r2*24 + 2*8 + hq];
                    }
                    #pragma unroll
                    for (int e = 0; e < 4; e++) {
                        float w = sWv21[(t*32 + hq*4 + e)*32 + lane];
                        u64 ww = pk2(w, w);
                        #pragma unroll
                        for (int r2 = 0; r2 < 4; r2++) {
                            fma2(oxy[r2], pk2(fcomp(xv[r2][0],e), fcomp(xv[r2][1],e)), ww);
                            ozv[r2] += w * fcomp(xv[r2][2], e);
                        }
                    }
                }
            }
            float v2x[4], v2y[4], v2z[4];
            #pragma unroll
            for (int r2 = 0; r2 < 4; r2++) {
                float ox, oy; upk2(ox, oy, oxy[r2]);
                float g = gg[p*4+r2];
                v2x[r2] = g*ox; v2y[r2] = g*oy; v2z[r2] = g*ozv[r2];
            }

            // ---- E: VNLeakyReLU ----
            __syncwarp();
            #pragma unroll
            for (int r2 = 0; r2 < 4; r2++) {
                ws[r2*96 +  0 + lane] = v2x[r2];
                ws[r2*96 + 32 + lane] = v2y[r2];
                ws[r2*96 + 64 + lane] = v2z[r2];
            }
            __syncwarp();
            u64 dxy[4] = {0ull,0ull,0ull,0ull};
            float dzv[4] = {0.f,0.f,0.f,0.f};
            for (int cq = 0; cq < 8; cq++) {
                float4 xv[4][3];
                #pragma unroll
                for (int r2 = 0; r2 < 4; r2++) {
                    xv[r2][0] = wsv4[r2*24 + 0*8 + cq];
                    xv[r2][1] = wsv4[r2*24 + 1*8 + cq];
                    xv[r2][2] = wsv4[r2*24 + 2*8 + cq];
                }
                #pragma unroll
                for (int e = 0; e < 4; e++) {
                    float w = sWd1[(cq*4 + e)*32 + lane];
                    u64 ww = pk2(w, w);
                    #pragma unroll
                    for (int r2 = 0; r2 < 4; r2++) {
                        fma2(dxy[r2], pk2(fcomp(xv[r2][0],e), fcomp(xv[r2][1],e)), ww);
                        dzv[r2] += w * fcomp(xv[r2][2], e);
                    }
                }
            }
            float v3x[4], v3y[4], v3z[4];
            #pragma unroll
            for (int r2 = 0; r2 < 4; r2++) {
                float dx, dy; upk2(dx, dy, dxy[r2]);
                float dz = dzv[r2];
                float dot = v2x[r2]*dx + v2y[r2]*dy + v2z[r2]*dz;
                float dsq = dx*dx + dy*dy + dz*dz;
                float tt  = dot / (dsq + 1e-6f);
                float rx = (dot >= 0.f) ? v2x[r2] : (v2x[r2] - tt*dx);
                float ry = (dot >= 0.f) ? v2y[r2] : (v2y[r2] - tt*dy);
                float rz = (dot >= 0.f) ? v2z[r2] : (v2z[r2] - tt*dz);
                v3x[r2] = 0.2f*v2x[r2] + 0.8f*rx;
                v3y[r2] = 0.2f*v2y[r2] + 0.8f*ry;
                v3z[r2] = 0.2f*v2z[r2] + 0.8f*rz;
            }

            // ---- F: layer 2 + output ----
            __syncwarp();
            #pragma unroll
            for (int r2 = 0; r2 < 4; r2++) {
                ws[r2*96 +  0 + lane] = v3x[r2];
                ws[r2*96 + 32 + lane] = v3y[r2];
                ws[r2*96 + 64 + lane] = v3z[r2];
            }
            __syncwarp();
            u64 bxy[4] = {0ull,0ull,0ull,0ull};
            float bzv[4] = {0.f,0.f,0.f,0.f};
            for (int cq = 0; cq < 8; cq++) {
                float4 xv[4][3];
                #pragma unroll
                for (int r2 = 0; r2 < 4; r2++) {
                    xv[r2][0] = wsv4[r2*24 + 0*8 + cq];
                    xv[r2][1] = wsv4[r2*24 + 1*8 + cq];
                    xv[r2][2] = wsv4[r2*24 + 2*8 + cq];
                }
                #pragma unroll
                for (int e = 0; e < 4; e++) {
                    float w = sWv12[(cq*4 + e)*32 + lane];
                    u64 ww = pk2(w, w);
                    #pragma unroll
                    for (int r2 = 0; r2 < 4; r2++) {
                        fma2(bxy[r2], pk2(fcomp(xv[r2][0],e), fcomp(xv[r2][1],e)), ww);
                        bzv[r2] += w * fcomp(xv[r2][2], e);
                    }
                }
            }
            float res[4];
            #pragma unroll
            for (int r2 = 0; r2 < 4; r2++) {
                float bx, by; upk2(bx, by, bxy[r2]);
                float bz = bzv[r2];
                float vn2 = sqrtf(bx*bx + by*by + bz*bz);
                float pp = vn2 * w2head + partB[p*4+r2];
                #pragma unroll
                for (int off = 16; off > 0; off >>= 1)
                    pp += __shfl_xor_sync(FULLMASK, pp, off);
                res[r2] = pp;
            }
            if (lane == 0) {
                int mb = base + p*4;
                if (mb + 3 < M) {
                    *(float4*)(out + mb) = make_float4(res[0], res[1], res[2], res[3]);
                } else {
                    #pragma unroll
                    for (int r2 = 0; r2 < 4; r2++)
                        if (mb + r2 < M) out[mb + r2] = res[r2];
                }
            }
        }
        __syncwarp();
    }
}

extern "C" void kernel_launch(void* const* d_in, const int* in_sizes, int n_in,
                              void* d_out, int out_size)
{
    const float* g_sca  = (const float*)d_in[0];
    const float* g_vec  = (const float*)d_in[1];
    const int*   g_idx  = (const int*)  d_in[2];
    const float* gWv11  = (const float*)d_in[3];
    const float* gWv21  = (const float*)d_in[4];
    const float* gWs1   = (const float*)d_in[5];
    const float* gWg1   = (const float*)d_in[6];
    const float* gbg1   = (const float*)d_in[7];
    const float* gWd1   = (const float*)d_in[8];
    const float* gWv12  = (const float*)d_in[9];
    const float* gWs2   = (const float*)d_in[11];
    float* out = (float*)d_out;
    const int M = in_sizes[2];

    const int smem_bytes = SMEM_FLOATS * (int)sizeof(float);  // 232192 B
    cudaFuncSetAttribute(frontier_vn_kernel,
                         cudaFuncAttributeMaxDynamicSharedMemorySize, smem_bytes);

    int sms = 148;
    cudaDeviceGetAttribute(&sms, cudaDevAttrMultiProcessorCount, 0);

    frontier_vn_kernel<<<sms, THREADS, smem_bytes>>>(
        g_sca, g_vec, g_idx,
        gWv11, gWv21, gWs1, gWg1, gbg1, gWd1, gWv12, gWs2,
        out, M);
}